// round 5
// baseline (speedup 1.0000x reference)
#include <cuda_runtime.h>

#define BB 8
#define CC 512
#define TT 8192
#define OPT 8               // outputs per thread
#define NT 256              // threads per block
#define CHUNK (NT * OPT)    // 2048 outputs per block
#define NCHUNK (TT / CHUNK) // 4 blocks per (b,c) row
#define HPAD 11             // smem halo stride (odd -> conflict-free)

__global__ __launch_bounds__(NT, 4) void aa_fused_kernel(
    const float* __restrict__ x,
    const float* __restrict__ alpha,
    const float* __restrict__ beta,
    const float* __restrict__ fu,
    const float* __restrict__ fd,
    float* __restrict__ out)
{
    __shared__ float s_h[NT * HPAD];           // halo exchange: 11264 B
    __shared__ float s_g0[6], s_g1[6], s_fd[12];
    __shared__ float s_a, s_ib;

    const int tid = threadIdx.x;
    const int bid = blockIdx.x;
    const int row = bid >> 2;      // NCHUNK == 4
    const int chunk = bid & 3;
    const int c = row & (CC - 1);

    // Stage filters (2x upsample gain folded in) + per-channel snake params.
    if (tid < 6)        s_g0[tid] = 2.0f * fu[10 - 2 * tid];                   // odd-n phase
    else if (tid < 12)  { int r = tid - 6; s_g1[r] = 2.0f * fu[11 - 2 * r]; }  // even-n phase
    else if (tid < 24)  s_fd[tid - 12] = fd[tid - 12];
    else if (tid == 24) s_a  = expf(alpha[c]);
    else if (tid == 25) s_ib = 1.0f / (expf(beta[c]) + 1e-9f);
    __syncthreads();

    float g0r[6], g1r[6], fdr[12];
    #pragma unroll
    for (int r = 0; r < 6; r++) { g0r[r] = s_g0[r]; g1r[r] = s_g1[r]; }
    #pragma unroll
    for (int q = 0; q < 12; q++) fdr[q] = s_fd[q];
    const float a  = s_a;
    const float ib = s_ib;

    const float* xrow = x + (size_t)row * TT;
    float* orow = out + (size_t)row * TT;
    const int tb = chunk * CHUNK + tid * OPT;

    // scalar clamped z for edges / block-boundary halo; n = upsampled index
    auto zval = [&](int n) -> float {
        n = min(max(n, 0), 2 * TT - 1);
        const int m = n >> 1;
        float acc = 0.0f;
        if (n & 1) {
            #pragma unroll
            for (int r = 0; r < 6; r++) {
                const int j = min(max(m - 2 + r, 0), TT - 1);
                acc += s_g0[r] * __ldg(&xrow[j]);
            }
        } else {
            #pragma unroll
            for (int r = 0; r < 6; r++) {
                const int j = min(max(m - 3 + r, 0), TT - 1);
                acc += s_g1[r] * __ldg(&xrow[j]);
            }
        }
        const float sv = __sinf(acc * a);
        return acc + sv * sv * ib;
    };

    // Z[s] ~ upsampled index n = 2*tb - 5 + s.  This thread owns s = 0..15;
    // s = 16..25 is the right neighbor's s' = 0..9 (n = 2*(tb+8)-5+s').
    float Z[26];

    // ---------- Phase A: own 16 z values ----------
    const bool fast = (tb >= 8) && (tb + 16 <= TT);
    if (fast) {
        // z[0..15] reads x[tb-5 .. tb+7]; aligned window x[tb-8 .. tb+7].
        float xw[16];
        const float4* xv = (const float4*)(xrow + tb - 8);
        #pragma unroll
        for (int i = 0; i < 4; i++) {
            float4 v = xv[i];
            xw[4 * i + 0] = v.x; xw[4 * i + 1] = v.y;
            xw[4 * i + 2] = v.z; xw[4 * i + 3] = v.w;
        }
        #pragma unroll
        for (int s = 0; s < 16; s++) {
            const int h = 3 + (s >> 1);          // window xw[h .. h+5], max 15
            float acc;
            if ((s & 1) == 0) {
                acc = g0r[0] * xw[h];
                #pragma unroll
                for (int r = 1; r < 6; r++) acc += g0r[r] * xw[h + r];
            } else {
                acc = g1r[0] * xw[h];
                #pragma unroll
                for (int r = 1; r < 6; r++) acc += g1r[r] * xw[h + r];
            }
            const float sv = __sinf(acc * a);
            Z[s] = acc + sv * sv * ib;
        }
    } else {
        // first thread of row / last thread of row: clamped path
        #pragma unroll
        for (int s = 0; s < 16; s++) Z[s] = zval(2 * tb - 5 + s);
    }

    // publish z[0..9] for the left neighbor
    #pragma unroll
    for (int j = 0; j < 10; j++) s_h[tid * HPAD + j] = Z[j];
    __syncthreads();

    // ---------- halo: neighbor's z[0..9] ----------
    if (tid < NT - 1) {
        #pragma unroll
        for (int j = 0; j < 10; j++) Z[16 + j] = s_h[(tid + 1) * HPAD + j];
    } else {
        // no right neighbor in block: recompute (clamped handles row end)
        #pragma unroll
        for (int j = 0; j < 10; j++) Z[16 + j] = zval(2 * tb + 11 + j);
    }

    // ---------- Phase B: downsample ----------
    // out[tb+i] = sum_q fd[q] * Z[2i+q]
    float o[OPT];
    #pragma unroll
    for (int i = 0; i < OPT; i++) {
        float acc = fdr[0] * Z[2 * i];
        #pragma unroll
        for (int q = 1; q < 12; q++) acc += fdr[q] * Z[2 * i + q];
        o[i] = acc;
    }
    float4* ov = (float4*)(orow + tb);
    ov[0] = make_float4(o[0], o[1], o[2], o[3]);
    ov[1] = make_float4(o[4], o[5], o[6], o[7]);
}

extern "C" void kernel_launch(void* const* d_in, const int* in_sizes, int n_in,
                              void* d_out, int out_size)
{
    const float* x     = (const float*)d_in[0];
    const float* alpha = (const float*)d_in[1];
    const float* beta  = (const float*)d_in[2];
    const float* fu    = (const float*)d_in[3];
    const float* fd    = (const float*)d_in[4];
    float* out = (float*)d_out;

    const int grid = BB * CC * NCHUNK; // 16384
    aa_fused_kernel<<<grid, NT>>>(x, alpha, beta, fu, fd, out);
}